// round 9
// baseline (speedup 1.0000x reference)
#include <cuda_runtime.h>

// ScaledDotProductAttention: B=8,H=12,S=1024,D=64, fp32, bool mask (serialized int32).
// Outputs: context [B,H,S,D] followed by attn [B,H,S,S] in d_out.
// One CTA per (b,h, 32-row query tile). Scores tile lives in smem.

#define B_ 8
#define H_ 12
#define S_ 1024
#define D_ 64
#define TQ 32
#define CK 64
#define NCHUNK (S_ / CK)      // 16
#define SS_STRIDE 1032        // padded, 16B-aligned, decorrelates banks across q
#define QS_STRIDE 68
#define KS_STRIDE 68
#define NTHREADS 256

__global__ __launch_bounds__(NTHREADS, 1)
void sdpa_kernel(const float* __restrict__ Qg_, const float* __restrict__ Kg_,
                 const float* __restrict__ Vg_, const int* __restrict__ Mg_,
                 float* __restrict__ ctx, float* __restrict__ attn)
{
    extern __shared__ float smem[];
    float* SS  = smem;                          // TQ * SS_STRIDE   (scores / probs)
    float* Qs  = SS  + TQ * SS_STRIDE;          // TQ * QS_STRIDE
    float* KV0 = Qs  + TQ * QS_STRIDE;          // CK * KS_STRIDE
    float* KV1 = KV0 + CK * KS_STRIDE;          // CK * KS_STRIDE

    const int tid = threadIdx.x;
    const int qt  = blockIdx.x;                 // 0..31
    const int h   = blockIdx.y;
    const int b   = blockIdx.z;
    const int bh  = b * H_ + h;
    const int q0g = qt * TQ;

    const float* Qg = Qg_ + ((size_t)bh * S_ + q0g) * D_;
    const float* Kg = Kg_ + (size_t)bh * S_ * D_;
    const float* Vg = Vg_ + (size_t)bh * S_ * D_;
    const int*   Mg = Mg_ + ((size_t)bh * S_ + q0g) * (size_t)S_;
    float* Ag = attn + ((size_t)bh * S_ + q0g) * (size_t)S_;
    float* Cg = ctx  + ((size_t)bh * S_ + q0g) * D_;

    // ---- load Q tile (32x64) into smem ----
    #pragma unroll
    for (int i = tid; i < TQ * D_ / 4; i += NTHREADS) {
        int q  = i / (D_ / 4);
        int d4 = i % (D_ / 4);
        float4 v = ((const float4*)Qg)[q * (D_ / 4) + d4];
        *(float4*)&Qs[q * QS_STRIDE + d4 * 4] = v;
    }

    const int tk = tid & 15;    // 0..15
    const int tq = tid >> 4;    // 0..15
    const int q0 = tq * 2;      // two q rows per thread

    const float scale = 0.125f; // 1/sqrt(64)

    // ================= Phase 1: scores = mask(Q K^T * scale) =================
    float4 pre[4];
    {   // preload chunk 0 into KV0
        #pragma unroll
        for (int j = 0; j < 4; j++) {
            int l = tid + NTHREADS * j;
            pre[j] = ((const float4*)Kg)[l];
        }
        #pragma unroll
        for (int j = 0; j < 4; j++) {
            int l = tid + NTHREADS * j;
            int r = l >> 4, c4 = l & 15;
            *(float4*)&KV0[r * KS_STRIDE + c4 * 4] = pre[j];
        }
    }

    for (int kc = 0; kc < NCHUNK; kc++) {
        __syncthreads();
        float* buf  = (kc & 1) ? KV1 : KV0;
        float* nbuf = (kc & 1) ? KV0 : KV1;

        if (kc + 1 < NCHUNK) {
            const float4* src = (const float4*)(Kg + (size_t)(kc + 1) * CK * D_);
            #pragma unroll
            for (int j = 0; j < 4; j++) pre[j] = src[tid + NTHREADS * j];
        }

        float acc[2][4] = {};
        #pragma unroll
        for (int d4 = 0; d4 < D_ / 4; d4++) {
            float4 qv0 = *(const float4*)&Qs[(q0    ) * QS_STRIDE + d4 * 4];
            float4 qv1 = *(const float4*)&Qs[(q0 + 1) * QS_STRIDE + d4 * 4];
            #pragma unroll
            for (int j = 0; j < 4; j++) {
                int kk = tk + 16 * j;
                float4 kv = *(const float4*)&buf[kk * KS_STRIDE + d4 * 4];
                acc[0][j] += qv0.x * kv.x + qv0.y * kv.y + qv0.z * kv.z + qv0.w * kv.w;
                acc[1][j] += qv1.x * kv.x + qv1.y * kv.y + qv1.z * kv.z + qv1.w * kv.w;
            }
        }

        // epilogue: scale, mask (int32 nonzero => masked), stash into SS
        #pragma unroll
        for (int iq = 0; iq < 2; iq++) {
            int qrow = q0 + iq;
            #pragma unroll
            for (int j = 0; j < 4; j++) {
                int c = kc * CK + tk + 16 * j;
                float v = acc[iq][j] * scale;
                if (Mg[(size_t)qrow * S_ + c] != 0) v = -1e9f;
                SS[qrow * SS_STRIDE + c] = v;
            }
        }

        if (kc + 1 < NCHUNK) {
            #pragma unroll
            for (int j = 0; j < 4; j++) {
                int l = tid + NTHREADS * j;
                int r = l >> 4, c4 = l & 15;
                *(float4*)&nbuf[r * KS_STRIDE + c4 * 4] = pre[j];
            }
        }
    }
    __syncthreads();

    // ================= Phase 2: softmax per row, write attn =================
    {
        const int warp = tid >> 5, lane = tid & 31;
        for (int r = warp; r < TQ; r += NTHREADS / 32) {
            float* row = SS + r * SS_STRIDE;
            float m = -1e30f;
            #pragma unroll 8
            for (int t = lane; t < S_; t += 32) m = fmaxf(m, row[t]);
            #pragma unroll
            for (int o = 16; o; o >>= 1) m = fmaxf(m, __shfl_xor_sync(0xffffffffu, m, o));
            float sum = 0.f;
            #pragma unroll 8
            for (int t = lane; t < S_; t += 32) {
                float p = __expf(row[t] - m);
                row[t] = p;
                sum += p;
            }
            #pragma unroll
            for (int o = 16; o; o >>= 1) sum += __shfl_xor_sync(0xffffffffu, sum, o);
            float inv = 1.0f / sum;
            float* arow = Ag + (size_t)r * S_;
            #pragma unroll 8
            for (int t = lane; t < S_; t += 32) {
                float p = row[t] * inv;
                row[t] = p;
                arow[t] = p;
            }
        }
    }
    __syncthreads();

    // ================= Phase 3: context = P @ V =================
    float acc2[2][4] = {};
    {   // preload V chunk 0 into KV0
        #pragma unroll
        for (int j = 0; j < 4; j++) {
            int l = tid + NTHREADS * j;
            pre[j] = ((const float4*)Vg)[l];
        }
        #pragma unroll
        for (int j = 0; j < 4; j++) {
            int l = tid + NTHREADS * j;
            int r = l >> 4, c4 = l & 15;
            *(float4*)&KV0[r * KS_STRIDE + c4 * 4] = pre[j];
        }
    }

    const int d0 = tk * 4;  // 4 contiguous output dims per thread
    for (int vc = 0; vc < NCHUNK; vc++) {
        __syncthreads();
        float* buf  = (vc & 1) ? KV1 : KV0;
        float* nbuf = (vc & 1) ? KV0 : KV1;

        if (vc + 1 < NCHUNK) {
            const float4* src = (const float4*)(Vg + (size_t)(vc + 1) * CK * D_);
            #pragma unroll
            for (int j = 0; j < 4; j++) pre[j] = src[tid + NTHREADS * j];
        }

        #pragma unroll
        for (int r4 = 0; r4 < CK / 4; r4++) {
            float pa0[4], pa1[4];
            *(float4*)pa0 = *(const float4*)&SS[(q0    ) * SS_STRIDE + vc * CK + r4 * 4];
            *(float4*)pa1 = *(const float4*)&SS[(q0 + 1) * SS_STRIDE + vc * CK + r4 * 4];
            #pragma unroll
            for (int rr = 0; rr < 4; rr++) {
                int r = r4 * 4 + rr;
                float4 vv = *(const float4*)&buf[r * KS_STRIDE + d0];
                acc2[0][0] += pa0[rr] * vv.x;  acc2[0][1] += pa0[rr] * vv.y;
                acc2[0][2] += pa0[rr] * vv.z;  acc2[0][3] += pa0[rr] * vv.w;
                acc2[1][0] += pa1[rr] * vv.x;  acc2[1][1] += pa1[rr] * vv.y;
                acc2[1][2] += pa1[rr] * vv.z;  acc2[1][3] += pa1[rr] * vv.w;
            }
        }

        if (vc + 1 < NCHUNK) {
            #pragma unroll
            for (int j = 0; j < 4; j++) {
                int l = tid + NTHREADS * j;
                int r = l >> 4, c4 = l & 15;
                *(float4*)&nbuf[r * KS_STRIDE + c4 * 4] = pre[j];
            }
        }
    }

    // write context
    #pragma unroll
    for (int iq = 0; iq < 2; iq++) {
        float4 o;
        o.x = acc2[iq][0]; o.y = acc2[iq][1]; o.z = acc2[iq][2]; o.w = acc2[iq][3];
        *(float4*)&Cg[(q0 + iq) * D_ + d0] = o;
    }
}

extern "C" void kernel_launch(void* const* d_in, const int* in_sizes, int n_in,
                              void* d_out, int out_size)
{
    const float* Q = (const float*)d_in[0];
    const float* K = (const float*)d_in[1];
    const float* V = (const float*)d_in[2];
    const int*   mask = (const int*)d_in[3];   // bool serialized as int32

    float* ctx  = (float*)d_out;                                   // [B,H,S,D]
    float* attn = ctx + (size_t)B_ * H_ * S_ * D_;                 // [B,H,S,S]

    const int smem_bytes = (TQ * SS_STRIDE + TQ * QS_STRIDE + 2 * CK * KS_STRIDE) * sizeof(float);
    cudaFuncSetAttribute(sdpa_kernel, cudaFuncAttributeMaxDynamicSharedMemorySize, smem_bytes);

    dim3 grid(S_ / TQ, H_, B_);
    dim3 block(NTHREADS);
    sdpa_kernel<<<grid, block, smem_bytes>>>(Q, K, V, mask, ctx, attn);
}

// round 14
// speedup vs baseline: 1.0601x; 1.0601x over previous
#include <cuda_runtime.h>
#include <cstdint>

// ScaledDotProductAttention: B=8,H=12,S=1024,D=64, fp32, bool mask (int32).
// Outputs: context [B,H,S,D] followed by attn [B,H,S,S] in d_out.
// One CTA per (b,h, 32-query tile).
// Phase 1: QK^T, 4q x 4k per thread, CK=128 chunks, scores -> transposed smem SS_T[c][q'].
// Phase 2: row softmax (writes attn).
// Phase 3: P@V, per V-row: 1 broadcast LDS.128 (4 probs) + LDS.64 (2 V dims) per lane.

#define B_ 8
#define H_ 12
#define S_ 1024
#define D_ 64
#define TQ 32
#define CK 128
#define NCHUNK (S_ / CK)      // 8
#define SST 36                // SS_T stride (words); 16B-aligned rows, q' packed
#define QS_STRIDE 68
#define KS_STRIDE 68
#define NTHREADS 256

__device__ __forceinline__ uint32_t sptr(const void* p) {
    return (uint32_t)__cvta_generic_to_shared(p);
}
__device__ __forceinline__ void cp16(uint32_t dst, const void* src) {
    asm volatile("cp.async.cg.shared.global [%0], [%1], 16;\n" :: "r"(dst), "l"(src));
}
__device__ __forceinline__ void cp_commit() { asm volatile("cp.async.commit_group;\n"); }
__device__ __forceinline__ void cp_wait0()  { asm volatile("cp.async.wait_group 0;\n"); }

__global__ __launch_bounds__(NTHREADS, 1)
void sdpa_kernel(const float* __restrict__ Qg_, const float* __restrict__ Kg_,
                 const float* __restrict__ Vg_, const int* __restrict__ Mg_,
                 float* __restrict__ ctx, float* __restrict__ attn)
{
    extern __shared__ float smem[];
    float* SS  = smem;                       // S_ * SST  (transposed scores [c][q'])
    float* Qs  = SS  + S_ * SST;             // TQ * QS_STRIDE
    float* KV0 = Qs  + TQ * QS_STRIDE;       // CK * KS_STRIDE
    float* KV1 = KV0 + CK * KS_STRIDE;       // CK * KS_STRIDE

    const int tid  = threadIdx.x;
    const int w    = tid >> 5;               // warp 0..7 (owns q rows w, w+8, w+16, w+24)
    const int lane = tid & 31;

    const int qt = blockIdx.x;               // 0..31
    const int bh = blockIdx.z * H_ + blockIdx.y;
    const int q0g = qt * TQ;

    const float* Qg = Qg_ + ((size_t)bh * S_ + q0g) * D_;
    const float* Kg = Kg_ + (size_t)bh * S_ * D_;
    const float* Vg = Vg_ + (size_t)bh * S_ * D_;
    const int*   Mg = Mg_ + ((size_t)bh * S_ + q0g) * (size_t)S_;
    float* Ag = attn + ((size_t)bh * S_ + q0g) * (size_t)S_;
    float* Cg = ctx  + ((size_t)bh * S_ + q0g) * D_;

    // ---- load Q tile (32x64) into smem ----
    #pragma unroll
    for (int i = tid; i < TQ * D_ / 4; i += NTHREADS) {
        int q  = i >> 4;
        int d4 = i & 15;
        float4 v = ((const float4*)Qg)[i];
        *(float4*)&Qs[q * QS_STRIDE + d4 * 4] = v;
    }

    // stage one CK x 64 fp32 tile (gmem -> smem) via cp.async
    auto stage = [&](float* dst, const float* src) {
        const float4* s4 = (const float4*)src;
        #pragma unroll
        for (int j = 0; j < (CK * D_ / 4) / NTHREADS; j++) {   // 8
            int l = tid + NTHREADS * j;
            int r = l >> 4, c4 = l & 15;
            cp16(sptr(&dst[r * KS_STRIDE + c4 * 4]), s4 + l);
        }
        cp_commit();
    };

    const float scale = 0.125f;  // 1/sqrt(64)

    // ================= Phase 1: scores = mask(Q K^T * scale) -> SS_T =================
    stage(KV0, Kg);

    for (int kc = 0; kc < NCHUNK; kc++) {
        cp_wait0();
        __syncthreads();
        float* buf  = (kc & 1) ? KV1 : KV0;
        float* nbuf = (kc & 1) ? KV0 : KV1;

        if (kc + 1 < NCHUNK) stage(nbuf, Kg + (size_t)(kc + 1) * CK * D_);

        // prefetch mask for this thread's 16 (q,c) cells (coalesced LDG.32)
        int mk[16];
        #pragma unroll
        for (int iq = 0; iq < 4; iq++)
            #pragma unroll
            for (int j = 0; j < 4; j++)
                mk[iq * 4 + j] = Mg[(size_t)(w + 8 * iq) * S_ + kc * CK + lane + 32 * j];

        float acc[4][4] = {};
        #pragma unroll 4
        for (int d4 = 0; d4 < D_ / 4; d4++) {
            float4 qv[4], kv[4];
            #pragma unroll
            for (int iq = 0; iq < 4; iq++)     // warp-broadcast loads
                qv[iq] = *(const float4*)&Qs[(w + 8 * iq) * QS_STRIDE + d4 * 4];
            #pragma unroll
            for (int j = 0; j < 4; j++)        // conflict-free (stride-68 rows)
                kv[j] = *(const float4*)&buf[(lane + 32 * j) * KS_STRIDE + d4 * 4];
            #pragma unroll
            for (int iq = 0; iq < 4; iq++)
                #pragma unroll
                for (int j = 0; j < 4; j++)
                    acc[iq][j] += qv[iq].x * kv[j].x + qv[iq].y * kv[j].y
                                + qv[iq].z * kv[j].z + qv[iq].w * kv[j].w;
        }

        // epilogue: scale, mask, store transposed: SS_T[c*SST + 4w + iq]
        #pragma unroll
        for (int iq = 0; iq < 4; iq++)
            #pragma unroll
            for (int j = 0; j < 4; j++) {
                int c = kc * CK + lane + 32 * j;
                float v = acc[iq][j] * scale;
                if (mk[iq * 4 + j] != 0) v = -1e9f;
                SS[(size_t)c * SST + 4 * w + iq] = v;
            }
    }

    // prefetch V chunk 0 now (overlaps softmax); KV0's last reader finished at kc=7's barrier
    stage(KV0, Vg);
    __syncthreads();   // all SS_T writes visible

    // ================= Phase 2: softmax per q row, write attn =================
    #pragma unroll
    for (int iq = 0; iq < 4; iq++) {
        const int q  = w + 8 * iq;
        const int qp = 4 * w + iq;
        float m = -1e30f;
        #pragma unroll 8
        for (int t = lane; t < S_; t += 32) m = fmaxf(m, SS[(size_t)t * SST + qp]);
        #pragma unroll
        for (int o = 16; o; o >>= 1) m = fmaxf(m, __shfl_xor_sync(0xffffffffu, m, o));
        float sum = 0.f;
        #pragma unroll 8
        for (int t = lane; t < S_; t += 32) {
            float p = __expf(SS[(size_t)t * SST + qp] - m);
            SS[(size_t)t * SST + qp] = p;
            sum += p;
        }
        #pragma unroll
        for (int o = 16; o; o >>= 1) sum += __shfl_xor_sync(0xffffffffu, sum, o);
        const float inv = 1.0f / sum;
        float* arow = Ag + (size_t)q * S_;
        #pragma unroll 8
        for (int t = lane; t < S_; t += 32) {
            float p = SS[(size_t)t * SST + qp] * inv;
            SS[(size_t)t * SST + qp] = p;
            arow[t] = p;
        }
    }

    // ================= Phase 3: context = P @ V =================
    float a00 = 0.f, a01 = 0.f, a10 = 0.f, a11 = 0.f;
    float a20 = 0.f, a21 = 0.f, a30 = 0.f, a31 = 0.f;
    const int d0 = 2 * lane;

    for (int vc = 0; vc < NCHUNK; vc++) {
        cp_wait0();
        __syncthreads();   // also orders phase-2 SS writes before first chunk's reads
        float* buf  = (vc & 1) ? KV1 : KV0;
        float* nbuf = (vc & 1) ? KV0 : KV1;

        if (vc + 1 < NCHUNK) stage(nbuf, Vg + (size_t)(vc + 1) * CK * D_);

        #pragma unroll 4
        for (int r = 0; r < CK; r++) {
            const int cg = vc * CK + r;
            float4 p4 = *(const float4*)&SS[(size_t)cg * SST + 4 * w];  // broadcast
            float2 v2 = *(const float2*)&buf[r * KS_STRIDE + d0];       // conflict-free
            a00 += p4.x * v2.x;  a01 += p4.x * v2.y;
            a10 += p4.y * v2.x;  a11 += p4.y * v2.y;
            a20 += p4.z * v2.x;  a21 += p4.z * v2.y;
            a30 += p4.w * v2.x;  a31 += p4.w * v2.y;
        }
    }

    // write context: q rows {w, w+8, w+16, w+24}, dims d0, d0+1
    float2 o0 = {a00, a01}, o1 = {a10, a11}, o2 = {a20, a21}, o3 = {a30, a31};
    *(float2*)&Cg[(w     ) * D_ + d0] = o0;
    *(float2*)&Cg[(w +  8) * D_ + d0] = o1;
    *(float2*)&Cg[(w + 16) * D_ + d0] = o2;
    *(float2*)&Cg[(w + 24) * D_ + d0] = o3;
}

extern "C" void kernel_launch(void* const* d_in, const int* in_sizes, int n_in,
                              void* d_out, int out_size)
{
    const float* Q = (const float*)d_in[0];
    const float* K = (const float*)d_in[1];
    const float* V = (const float*)d_in[2];
    const int*   mask = (const int*)d_in[3];   // bool serialized as int32

    float* ctx  = (float*)d_out;                                   // [B,H,S,D]
    float* attn = ctx + (size_t)B_ * H_ * S_ * D_;                 // [B,H,S,S]

    const int smem_bytes = (S_ * SST + TQ * QS_STRIDE + 2 * CK * KS_STRIDE) * sizeof(float);
    cudaFuncSetAttribute(sdpa_kernel, cudaFuncAttributeMaxDynamicSharedMemorySize, smem_bytes);

    dim3 grid(S_ / TQ, H_, B_);
    dim3 block(NTHREADS);
    sdpa_kernel<<<grid, block, smem_bytes>>>(Q, K, V, mask, ctx, attn);
}

// round 15
// speedup vs baseline: 1.0614x; 1.0012x over previous
#include <cuda_runtime.h>
#include <cstdint>

// ScaledDotProductAttention: B=8,H=12,S=1024,D=64, fp32, bool mask (int32).
// Outputs: context [B,H,S,D] followed by attn [B,H,S,S] in d_out.
// One CTA per (b,h, 32-query tile).
// Phase 1: QK^T, 4q x 4k per thread, CK=128 chunks, scores -> transposed smem SS_T[c][q'].
// Phase 2: row softmax (writes attn).
// Phase 3: P@V, per V-row: 1 broadcast LDS.128 (4 probs) + LDS.64 (2 V dims) per lane.

#define B_ 8
#define H_ 12
#define S_ 1024
#define D_ 64
#define TQ 32
#define CK 128
#define NCHUNK (S_ / CK)      // 8
#define SST 36                // SS_T stride (words); 16B-aligned rows, q' packed
#define QS_STRIDE 68
#define KS_STRIDE 68
#define NTHREADS 256

__device__ __forceinline__ uint32_t sptr(const void* p) {
    return (uint32_t)__cvta_generic_to_shared(p);
}
__device__ __forceinline__ void cp16(uint32_t dst, const void* src) {
    asm volatile("cp.async.cg.shared.global [%0], [%1], 16;\n" :: "r"(dst), "l"(src));
}
__device__ __forceinline__ void cp_commit() { asm volatile("cp.async.commit_group;\n"); }
__device__ __forceinline__ void cp_wait0()  { asm volatile("cp.async.wait_group 0;\n"); }

__global__ __launch_bounds__(NTHREADS, 1)
void sdpa_kernel(const float* __restrict__ Qg_, const float* __restrict__ Kg_,
                 const float* __restrict__ Vg_, const int* __restrict__ Mg_,
                 float* __restrict__ ctx, float* __restrict__ attn)
{
    extern __shared__ float smem[];
    float* SS  = smem;                       // S_ * SST  (transposed scores [c][q'])
    float* Qs  = SS  + S_ * SST;             // TQ * QS_STRIDE
    float* KV0 = Qs  + TQ * QS_STRIDE;       // CK * KS_STRIDE
    float* KV1 = KV0 + CK * KS_STRIDE;       // CK * KS_STRIDE

    const int tid  = threadIdx.x;
    const int w    = tid >> 5;               // warp 0..7 (owns q rows w, w+8, w+16, w+24)
    const int lane = tid & 31;

    const int qt = blockIdx.x;               // 0..31
    const int bh = blockIdx.z * H_ + blockIdx.y;
    const int q0g = qt * TQ;

    const float* Qg = Qg_ + ((size_t)bh * S_ + q0g) * D_;
    const float* Kg = Kg_ + (size_t)bh * S_ * D_;
    const float* Vg = Vg_ + (size_t)bh * S_ * D_;
    const int*   Mg = Mg_ + ((size_t)bh * S_ + q0g) * (size_t)S_;
    float* Ag = attn + ((size_t)bh * S_ + q0g) * (size_t)S_;
    float* Cg = ctx  + ((size_t)bh * S_ + q0g) * D_;

    // ---- load Q tile (32x64) into smem ----
    #pragma unroll
    for (int i = tid; i < TQ * D_ / 4; i += NTHREADS) {
        int q  = i >> 4;
        int d4 = i & 15;
        float4 v = ((const float4*)Qg)[i];
        *(float4*)&Qs[q * QS_STRIDE + d4 * 4] = v;
    }

    // stage one CK x 64 fp32 tile (gmem -> smem) via cp.async
    auto stage = [&](float* dst, const float* src) {
        const float4* s4 = (const float4*)src;
        #pragma unroll
        for (int j = 0; j < (CK * D_ / 4) / NTHREADS; j++) {   // 8
            int l = tid + NTHREADS * j;
            int r = l >> 4, c4 = l & 15;
            cp16(sptr(&dst[r * KS_STRIDE + c4 * 4]), s4 + l);
        }
        cp_commit();
    };

    const float scale = 0.125f;  // 1/sqrt(64)

    // ================= Phase 1: scores = mask(Q K^T * scale) -> SS_T =================
    stage(KV0, Kg);

    for (int kc = 0; kc < NCHUNK; kc++) {
        cp_wait0();
        __syncthreads();
        float* buf  = (kc & 1) ? KV1 : KV0;
        float* nbuf = (kc & 1) ? KV0 : KV1;

        if (kc + 1 < NCHUNK) stage(nbuf, Kg + (size_t)(kc + 1) * CK * D_);

        // prefetch mask for this thread's 16 (q,c) cells (coalesced LDG.32)
        int mk[16];
        #pragma unroll
        for (int iq = 0; iq < 4; iq++)
            #pragma unroll
            for (int j = 0; j < 4; j++)
                mk[iq * 4 + j] = Mg[(size_t)(w + 8 * iq) * S_ + kc * CK + lane + 32 * j];

        float acc[4][4] = {};
        #pragma unroll 4
        for (int d4 = 0; d4 < D_ / 4; d4++) {
            float4 qv[4], kv[4];
            #pragma unroll
            for (int iq = 0; iq < 4; iq++)     // warp-broadcast loads
                qv[iq] = *(const float4*)&Qs[(w + 8 * iq) * QS_STRIDE + d4 * 4];
            #pragma unroll
            for (int j = 0; j < 4; j++)        // conflict-free (stride-68 rows)
                kv[j] = *(const float4*)&buf[(lane + 32 * j) * KS_STRIDE + d4 * 4];
            #pragma unroll
            for (int iq = 0; iq < 4; iq++)
                #pragma unroll
                for (int j = 0; j < 4; j++)
                    acc[iq][j] += qv[iq].x * kv[j].x + qv[iq].y * kv[j].y
                                + qv[iq].z * kv[j].z + qv[iq].w * kv[j].w;
        }

        // epilogue: scale, mask, store transposed: SS_T[c*SST + 4w + iq]
        #pragma unroll
        for (int iq = 0; iq < 4; iq++)
            #pragma unroll
            for (int j = 0; j < 4; j++) {
                int c = kc * CK + lane + 32 * j;
                float v = acc[iq][j] * scale;
                if (mk[iq * 4 + j] != 0) v = -1e9f;
                SS[(size_t)c * SST + 4 * w + iq] = v;
            }
    }

    // prefetch V chunk 0 now (overlaps softmax); KV0's last reader finished at kc=7's barrier
    stage(KV0, Vg);
    __syncthreads();   // all SS_T writes visible

    // ================= Phase 2: softmax per q row, write attn =================
    #pragma unroll
    for (int iq = 0; iq < 4; iq++) {
        const int q  = w + 8 * iq;
        const int qp = 4 * w + iq;
        float m = -1e30f;
        #pragma unroll 8
        for (int t = lane; t < S_; t += 32) m = fmaxf(m, SS[(size_t)t * SST + qp]);
        #pragma unroll
        for (int o = 16; o; o >>= 1) m = fmaxf(m, __shfl_xor_sync(0xffffffffu, m, o));
        float sum = 0.f;
        #pragma unroll 8
        for (int t = lane; t < S_; t += 32) {
            float p = __expf(SS[(size_t)t * SST + qp] - m);
            SS[(size_t)t * SST + qp] = p;
            sum += p;
        }
        #pragma unroll
        for (int o = 16; o; o >>= 1) sum += __shfl_xor_sync(0xffffffffu, sum, o);
        const float inv = 1.0f / sum;
        float* arow = Ag + (size_t)q * S_;
        #pragma unroll 8
        for (int t = lane; t < S_; t += 32) {
            float p = SS[(size_t)t * SST + qp] * inv;
            SS[(size_t)t * SST + qp] = p;
            arow[t] = p;
        }
    }

    // ================= Phase 3: context = P @ V =================
    float a00 = 0.f, a01 = 0.f, a10 = 0.f, a11 = 0.f;
    float a20 = 0.f, a21 = 0.f, a30 = 0.f, a31 = 0.f;
    const int d0 = 2 * lane;

    for (int vc = 0; vc < NCHUNK; vc++) {
        cp_wait0();
        __syncthreads();   // also orders phase-2 SS writes before first chunk's reads
        float* buf  = (vc & 1) ? KV1 : KV0;
        float* nbuf = (vc & 1) ? KV0 : KV1;

        if (vc + 1 < NCHUNK) stage(nbuf, Vg + (size_t)(vc + 1) * CK * D_);

        #pragma unroll 4
        for (int r = 0; r < CK; r++) {
            const int cg = vc * CK + r;
            float4 p4 = *(const float4*)&SS[(size_t)cg * SST + 4 * w];  // broadcast
            float2 v2 = *(const float2*)&buf[r * KS_STRIDE + d0];       // conflict-free
            a00 += p4.x * v2.x;  a01 += p4.x * v2.y;
            a10 += p4.y * v2.x;  a11 += p4.y * v2.y;
            a20 += p4.z * v2.x;  a21 += p4.z * v2.y;
            a30 += p4.w * v2.x;  a31 += p4.w * v2.y;
        }
    }

    // write context: q rows {w, w+8, w+16, w+24}, dims d0, d0+1
    float2 o0 = {a00, a01}, o1 = {a10, a11}, o2 = {a20, a21}, o3 = {a30, a31};
    *(float2*)&Cg[(w     ) * D_ + d0] = o0;
    *(float2*)&Cg[(w +  8) * D_ + d0] = o1;
    *(float2*)&Cg[(w + 16) * D_ + d0] = o2;
    *(float2*)&Cg[(w + 24) * D_ + d0] = o3;
}

extern "C" void kernel_launch(void* const* d_in, const int* in_sizes, int n_in,
                              void* d_out, int out_size)
{
    const float* Q = (const float*)d_in[0];
    const float* K = (const float*)d_in[1];
    const float* V = (const float*)d_in[2];
    const int*   mask = (const int*)d_in[3];   // bool serialized as int32

    float* ctx  = (float*)d_out;                                   // [B,H,S,D]
    float* attn = ctx + (size_t)B_ * H_ * S_ * D_;                 // [B,H,S,S]

    const int smem_bytes = (S_ * SST + TQ * QS_STRIDE + 2 * CK * KS_STRIDE) * sizeof(float);
    cudaFuncSetAttribute(sdpa_kernel, cudaFuncAttributeMaxDynamicSharedMemorySize, smem_bytes);

    dim3 grid(S_ / TQ, H_, B_);
    dim3 block(NTHREADS);
    sdpa_kernel<<<grid, block, smem_bytes>>>(Q, K, V, mask, ctx, attn);
}